// round 17
// baseline (speedup 1.0000x reference)
#include <cuda_runtime.h>
#include <cuda_fp16.h>
#include <cstdint>
#include <math.h>

#define IMG   512
#define NANG  180
#define NBAT  4
#define NZ    4            // angle splits
#define HANG  (NANG / NZ)  // 45 angles per z-slice
#define CH    3            // angles per staged chunk (double-buffered), 45 % 3 == 0
#define NCZ   (HANG / CH)  // 15 chunks per slice
#define GROW  704          // padded global row (sample-quads): 64 zeros | 512 data | 128 zeros

// ---------------- scratch (no allocations allowed) ----------------
__device__ float  g_ff[IMG];                              // frequency-domain filter
__device__ float  g_h[IMG];                               // spatial filter kernel
__device__ float2 g_trig[NANG];                           // (sin, cos) per angle
__device__ __align__(16) __half g_filth[NANG][GROW * 4];  // filtered rows, fp16 batch-quads, padded
__device__ __align__(16) float4 g_part[NZ][IMG * IMG];    // per-slice partial sums

__device__ __forceinline__ void cp_async16(unsigned int smem_addr, const void* gptr) {
    asm volatile("cp.async.ca.shared.global [%0], [%1], 16;\n"
                 :: "r"(smem_addr), "l"(gptr) : "memory");
}
__device__ __forceinline__ void cp_async_commit() {
    asm volatile("cp.async.commit_group;\n" ::: "memory");
}
template <int N>
__device__ __forceinline__ void cp_async_wait() {
    asm volatile("cp.async.wait_group %0;\n" :: "n"(N) : "memory");
}
// packed f32x2 accumulate: a += b
__device__ __forceinline__ void addf32x2(float2& a, float2 b) {
    unsigned long long ua = reinterpret_cast<unsigned long long&>(a);
    unsigned long long ub = reinterpret_cast<unsigned long long&>(b);
    asm("add.rn.f32x2 %0, %1, %2;" : "=l"(ua) : "l"(ua), "l"(ub));
    reinterpret_cast<unsigned long long&>(a) = ua;
}

// ---------------- setup stage 1: one warp per k ----------------
__global__ void setup_ff() {                // grid 512, block 32
    const int k = blockIdx.x;
    const int t = threadIdx.x;
    float acc = 0.0f;
    #pragma unroll
    for (int i = 0; i < 8; ++i) {
        int jidx = t * 8 + i;               // 0..255, j = 2*jidx+1
        int jj = 2 * jidx + 1;
        int m = (jj <= 255) ? jj : (IMG - jj);
        float pm = (float)M_PI * (float)m;
        float fj = -1.0f / (pm * pm);
        int idx = (jj * k) & (IMG - 1);
        acc = fmaf(fj, cospif((float)idx * (1.0f / 256.0f)), acc);
    }
    #pragma unroll
    for (int o = 16; o; o >>= 1) acc += __shfl_xor_sync(0xffffffffu, acc, o);
    if (t == 0) {
        float ffk = 2.0f * (0.25f + acc);
        if (k > 0) {
            int m = (k <= 256) ? k : (IMG - k);          // |fftfreq|*N
            float x = (float)m * (1.0f / (float)IMG);    // exact
            ffk *= sinpif(x) / ((float)M_PI * x);        // sin(omega)/omega, even
        }
        g_ff[k] = ffk;
        if (k < NANG) {
            double th = (double)k * (M_PI / 179.0);      // linspace(0,180,180) deg
            g_trig[k] = make_float2((float)sin(th), (float)cos(th));
        }
    }
}

// ---------------- setup stage 2: one block per q ----------------
__global__ void setup_h() {                 // grid 512, block 128
    __shared__ float s_part[4];
    const int q = blockIdx.x;
    const int t = threadIdx.x;
    float acc = 0.0f;
    #pragma unroll
    for (int u = 0; u < 4; ++u) {
        int k = t * 4 + u;
        int idx = (k * q) & (IMG - 1);
        acc = fmaf(__ldg(&g_ff[k]), cospif((float)idx * (1.0f / 256.0f)), acc);
    }
    #pragma unroll
    for (int o = 16; o; o >>= 1) acc += __shfl_xor_sync(0xffffffffu, acc, o);
    if ((t & 31) == 0) s_part[t >> 5] = acc;
    __syncthreads();
    if (t == 0)
        g_h[q] = ((s_part[0] + s_part[1]) + (s_part[2] + s_part[3])) * (1.0f / (float)IMG);
}

// ---------------- filtering: circular conv + write padded fp16 batch-quad rows ----------------
__global__ void filter_kernel(const float* __restrict__ sino) {
    __shared__ float s_row[2 * IMG];   // row duplicated -> no modulo
    __shared__ float s_hr[IMG];
    const int a = blockIdx.x;
    const int b = blockIdx.y;
    const int t = threadIdx.x;         // 0..127

    float4 r4 = reinterpret_cast<const float4*>(sino + (b * NANG + a) * IMG)[t];
    reinterpret_cast<float4*>(s_row)[t]       = r4;
    reinterpret_cast<float4*>(s_row)[t + 128] = r4;

    float4 h4 = reinterpret_cast<const float4*>(g_h)[t];   // h[4t..4t+3]
    s_hr[(IMG - (4 * t + 0)) & (IMG - 1)] = h4.x;
    s_hr[(IMG - (4 * t + 1)) & (IMG - 1)] = h4.y;
    s_hr[(IMG - (4 * t + 2)) & (IMG - 1)] = h4.z;
    s_hr[(IMG - (4 * t + 3)) & (IMG - 1)] = h4.w;

    // zero the global pads (sample-quads, 8B each) for this angle
    uint2* rowq = reinterpret_cast<uint2*>(&g_filth[a][0]);
    if (b == 0) {
        if (t < 64) rowq[t] = make_uint2(0u, 0u);            // samples 0..63
    } else if (b == 1) {
        rowq[576 + t] = make_uint2(0u, 0u);                  // samples 576..703
    }
    __syncthreads();

    float acc0 = 0.f, acc1 = 0.f, acc2 = 0.f, acc3 = 0.f;
    const int obase = 4 * t;
    float4 R0 = *reinterpret_cast<const float4*>(&s_row[obase]);
    #pragma unroll 4
    for (int u = 0; u < IMG; u += 4) {
        float4 HR = *reinterpret_cast<const float4*>(&s_hr[u]);                   // broadcast
        float4 R1 = *reinterpret_cast<const float4*>(&s_row[obase + u + 4]);      // sliding
        acc0 = fmaf(R0.x, HR.x, fmaf(R0.y, HR.y, fmaf(R0.z, HR.z, fmaf(R0.w, HR.w, acc0))));
        acc1 = fmaf(R0.y, HR.x, fmaf(R0.z, HR.y, fmaf(R0.w, HR.z, fmaf(R1.x, HR.w, acc1))));
        acc2 = fmaf(R0.z, HR.x, fmaf(R0.w, HR.y, fmaf(R1.x, HR.z, fmaf(R1.y, HR.w, acc2))));
        acc3 = fmaf(R0.w, HR.x, fmaf(R1.x, HR.y, fmaf(R1.y, HR.z, fmaf(R1.z, HR.w, acc3))));
        R0 = R1;
    }

    // scatter into fp16 batch-quad layout: sample (64+obase+i), component b
    __half* dsth = &g_filth[a][64 * 4];
    dsth[(obase + 0) * 4 + b] = __float2half_rn(acc0);
    dsth[(obase + 1) * 4 + b] = __float2half_rn(acc1);
    dsth[(obase + 2) * 4 + b] = __float2half_rn(acc2);
    dsth[(obase + 3) * 4 + b] = __float2half_rn(acc3);
}

// ---------------- backprojection: 32x32 tile, grid.z=NZ angle slices, fp16 lerp ------------
// Each z-slice accumulates HANG angles into g_part[z]. Early-out tiles write nothing;
// all their pixels are outside the circle, so reduce masks them to exactly 0.
__global__ __launch_bounds__(512) void backproj_kernel() {
    __shared__ uint2  s_win[2][CH][64];     // 3 KB, double-buffered fp16 windows
    __shared__ float4 s_meta[2][CH];        // (sin, cos, offset, -)
    __shared__ float2 s_trig[HANG];

    const int t  = threadIdx.x;
    const int tx = t & 31;
    const int ty = t >> 5;             // 0..15
    const int w  = blockIdx.x * 32 + tx;
    const int y0 = blockIdx.y * 32 + ty;
    const int az0 = blockIdx.z * HANG;

    const float xf  = 255.0f - (float)w;
    const float yfa = (float)y0 - 256.0f;
    const float yfb = (float)(y0 + 16) - 256.0f;

    // block-level circle early-out (tile entirely outside radius 256)
    {
        float xhi = 255.0f - (float)(blockIdx.x * 32);
        float xlo = xhi - 31.0f;
        float ylo = (float)(blockIdx.y * 32) - 256.0f;
        float yhi = ylo + 31.0f;
        float mx = (xlo <= 0.0f && 0.0f <= xhi) ? 0.0f : fminf(fabsf(xlo), fabsf(xhi));
        float my = (ylo <= 0.0f && 0.0f <= yhi) ? 0.0f : fminf(fabsf(ylo), fabsf(yhi));
        if (fmaf(mx, mx, my * my) > 65536.0f) return;   // reduce kernel masks these pixels
    }

    if (t < HANG) s_trig[t] = g_trig[az0 + t];
    __syncthreads();                   // trig visible before staging

    const float xfmin = 224.0f - 32.0f * (float)blockIdx.x;
    const float yfmin = 32.0f * (float)blockIdx.y - 256.0f;
    const float yfmax = yfmin + 31.0f;

    const unsigned int sbase = (unsigned int)__cvta_generic_to_shared(&s_win[0][0][0]);

    const int st_ang = t >> 5;         // 0..2 for t < 96
    const int st_j   = t & 31;         // 0..31, each covers 2 sample-quads (16B)

    auto stage = [&](int c, int buf) {
        if (t < CH * 32) {
            float2 sc = s_trig[c * CH + st_ang];
            float t0  = fmaf(xfmin, sc.x, 256.0f);
            float pmw = fminf(fmaf(yfmin, sc.y, t0), fmaf(yfmax, sc.y, t0));
            int base  = ((int)floorf(pmw)) & ~1;      // even -> 16B-aligned window start
            const __half* src = &g_filth[az0 + c * CH + st_ang][(64 + base - 2 + 2 * st_j) * 4];
            unsigned int dst = sbase + (unsigned int)(((buf * CH + st_ang) * 64 + 2 * st_j) * 8);
            cp_async16(dst, src);
            if (st_j == 0)
                s_meta[buf][st_ang] = make_float4(sc.x, sc.y, 258.0f - (float)base, 0.f);
            cp_async_commit();
        }
    };

    stage(0, 0);

    float2 ac0A = {0.f, 0.f}, ac0B = {0.f, 0.f};   // pixel a (y0): batches 01, 23
    float2 ac1A = {0.f, 0.f}, ac1B = {0.f, 0.f};   // pixel b (y0+16)

    for (int c = 0; c < NCZ; ++c) {
        if (c + 1 < NCZ) { stage(c + 1, (c + 1) & 1); cp_async_wait<1>(); }
        else             { cp_async_wait<0>(); }
        __syncthreads();

        #pragma unroll
        for (int ci = 0; ci < CH; ++ci) {
            const float4 m  = s_meta[c & 1][ci];        // sin, cos, offset
            const float  pq = fmaf(xf, m.x, m.z);
            const uint2* win = s_win[c & 1][ci];

            // pixel a
            {
                float q   = fmaf(yfa, m.y, pq);
                float fl  = floorf(q);
                float fr  = q - fl;
                int   il  = (int)fl;
                __half2 fr2 = __float2half2_rn(fr);
                uint2 u0 = win[il];
                uint2 u1 = win[il + 1];
                __half2 v0a = *reinterpret_cast<__half2*>(&u0.x);
                __half2 v0b = *reinterpret_cast<__half2*>(&u0.y);
                __half2 v1a = *reinterpret_cast<__half2*>(&u1.x);
                __half2 v1b = *reinterpret_cast<__half2*>(&u1.y);
                __half2 la = __hfma2(fr2, __hsub2(v1a, v0a), v0a);
                __half2 lb = __hfma2(fr2, __hsub2(v1b, v0b), v0b);
                addf32x2(ac0A, __half22float2(la));
                addf32x2(ac0B, __half22float2(lb));
            }
            // pixel b
            {
                float q   = fmaf(yfb, m.y, pq);
                float fl  = floorf(q);
                float fr  = q - fl;
                int   il  = (int)fl;
                __half2 fr2 = __float2half2_rn(fr);
                uint2 u0 = win[il];
                uint2 u1 = win[il + 1];
                __half2 v0a = *reinterpret_cast<__half2*>(&u0.x);
                __half2 v0b = *reinterpret_cast<__half2*>(&u0.y);
                __half2 v1a = *reinterpret_cast<__half2*>(&u1.x);
                __half2 v1b = *reinterpret_cast<__half2*>(&u1.y);
                __half2 la = __hfma2(fr2, __hsub2(v1a, v0a), v0a);
                __half2 lb = __hfma2(fr2, __hsub2(v1b, v0b), v0b);
                addf32x2(ac1A, __half22float2(la));
                addf32x2(ac1B, __half22float2(lb));
            }
        }
        __syncthreads();               // protect windows/meta before next overwrite
    }

    g_part[blockIdx.z][y0 * IMG + w]        = make_float4(ac0A.x, ac0A.y, ac0B.x, ac0B.y);
    g_part[blockIdx.z][(y0 + 16) * IMG + w] = make_float4(ac1A.x, ac1A.y, ac1B.x, ac1B.y);
}

// ---------------- reduce: add slices, apply circle mask + pi/(2A), planar output ----------
__global__ __launch_bounds__(512) void reduce_kernel(float* __restrict__ out) {
    const int pix = blockIdx.x * 512 + threadIdx.x;
    const float4 p0 = g_part[0][pix];
    const float4 p1 = g_part[1][pix];
    const float4 p2 = g_part[2][pix];
    const float4 p3 = g_part[3][pix];
    const int x = pix & (IMG - 1);
    const int y = pix >> 9;
    const float xf = 255.0f - (float)x;
    const float yf = (float)y - 256.0f;
    const float g = (fmaf(xf, xf, yf * yf) <= 65536.0f) ? (float)(M_PI / (2.0 * NANG)) : 0.0f;
    out[0 * IMG * IMG + pix] = ((p0.x + p1.x) + (p2.x + p3.x)) * g;
    out[1 * IMG * IMG + pix] = ((p0.y + p1.y) + (p2.y + p3.y)) * g;
    out[2 * IMG * IMG + pix] = ((p0.z + p1.z) + (p2.z + p3.z)) * g;
    out[3 * IMG * IMG + pix] = ((p0.w + p1.w) + (p2.w + p3.w)) * g;
}

// ---------------- launcher ----------------
extern "C" void kernel_launch(void* const* d_in, const int* in_sizes, int n_in,
                              void* d_out, int out_size) {
    const float* sino = (const float*)d_in[0];
    float* out = (float*)d_out;

    setup_ff<<<512, 32>>>();
    setup_h<<<512, 128>>>();
    filter_kernel<<<dim3(NANG, NBAT), 128>>>(sino);
    backproj_kernel<<<dim3(IMG / 32, IMG / 32, NZ), 512>>>();
    reduce_kernel<<<IMG * IMG / 512, 512>>>(out);
}